// round 9
// baseline (speedup 1.0000x reference)
#include <cuda_runtime.h>
#include <cstddef>

// Problem constants (from reference setup_inputs)
#define B      64
#define S      2048
#define D      768
#define D4     (D / 4)          // 192 float4 per row
#define POOL   32
#define L      8
#define NT     10
#define TOPK   4
#define T_OUT  (L + TOPK * L + 1 + S)   // 2089
#define X_OFF  (L + TOPK * L + 1)       // 41

#define ROWS   64
#define CHUNKS (S / ROWS)       // 32

// Scratch. g_partial: every slot written exactly once per launch.
// g_cnt: scheduling-only atomics (zero-init at load; finisher resets to 0
// after use so every graph replay starts clean). The finisher election
// never waits/spins, so there is no deadlock path.
__device__ float g_partial[(size_t)B * CHUNKS * D];
__device__ int   g_cnt[B];

// -------------------------------------------------------------------------
// Single fused kernel.
// Grid (CHUNKS+1, B), block = 192 threads (6 warps).
//   chunk <  CHUNKS : copy 64 rows of x -> out[:, X_OFF+chunk*64, :]
//                     (streaming loads/stores) + per-chunk column sums.
//                     Last chunk to finish for batch b runs the selection
//                     epilogue for b (hidden under other batches' copies).
//   chunk == CHUNKS : selection-independent rows (g-prompt + cls).
// -------------------------------------------------------------------------
__global__ __launch_bounds__(D4) void fused_kernel(
    const float4* __restrict__ x, float4* __restrict__ out,
    const float4* __restrict__ g_prompts, const float4* __restrict__ cls_token,
    const float*  __restrict__ e_keys,    const float4* __restrict__ e_prompts,
    const int*    __restrict__ task_id_p)
{
    const int chunk = blockIdx.x;
    const int b     = blockIdx.y;
    const int t     = threadIdx.x;          // 0..191
    const int lane  = t & 31;
    const int warp  = t >> 5;               // 0..5

    if (chunk == CHUNKS) {
        // static rows: g-prompt rows [0,8), cls row 40
        float4* obase = out + (size_t)b * T_OUT * D4;
        const int task = *task_id_p;
        const float4* gsrc = g_prompts + (size_t)task * L * D4;
#pragma unroll
        for (int i = 0; i < L; i++)
            obase[i * D4 + t] = gsrc[i * D4 + t];
        obase[(size_t)(L + TOPK * L) * D4 + t] = cls_token[t];
        return;
    }

    // ---------------- bulk copy + chunk partial sums ----------------
    {
        const float4* __restrict__ xrow =
            x + ((size_t)b * S + (size_t)chunk * ROWS) * D4 + t;
        float4* __restrict__ orow =
            out + ((size_t)b * T_OUT + X_OFF + (size_t)chunk * ROWS) * D4 + t;

        float4 acc = make_float4(0.f, 0.f, 0.f, 0.f);

#pragma unroll 16
        for (int r = 0; r < ROWS; r++) {
            float4 v = __ldcs(xrow + (size_t)r * D4);   // streaming: no reuse
            __stcs(orow + (size_t)r * D4, v);           // streaming: no reuse
            acc.x += v.x; acc.y += v.y; acc.z += v.z; acc.w += v.w;
        }

        float4* p = reinterpret_cast<float4*>(g_partial);
        p[((size_t)b * CHUNKS + chunk) * D4 + t] = acc; // normal store (L2 reuse)
    }

    // ---------------- last-block-per-batch epilogue ----------------
    __shared__ int  s_last;
    __shared__ float q[D];
    __shared__ float sim[POOL];
    __shared__ int   sel[TOPK];

    __threadfence();                         // release partials device-wide
    if (t == 0) {
        int old = atomicAdd(&g_cnt[b], 1);
        s_last = (old == CHUNKS - 1);
    }
    __syncthreads();
    if (!s_last) return;
    __threadfence();                         // acquire: partials now visible

    // -- query reduce: 4 columns per thread, partials are L2-resident --
#pragma unroll
    for (int j = 0; j < 4; j++) {
        const int d = t + j * D4;            // 192*4 = 768
        const float* p = g_partial + (size_t)b * CHUNKS * D + d;
        float s = 0.f;
#pragma unroll
        for (int c = 0; c < CHUNKS; c++) s += p[(size_t)c * D];
        q[d] = s;
    }
    __syncthreads();

    // -- similarity: 6 warps cover 32 pools (query-norm & /S are common
    //    positive scales -> irrelevant to top-k ordering) --
    for (int p = warp; p < POOL; p += 6) {
        const float* key = e_keys + (size_t)p * D;
        float dot = 0.f, ksq = 0.f;
#pragma unroll
        for (int j = 0; j < D / 32; j++) {
            const int d = lane + j * 32;
            const float k = key[d];
            dot += q[d] * k;
            ksq += k * k;
        }
#pragma unroll
        for (int off = 16; off > 0; off >>= 1) {
            dot += __shfl_xor_sync(0xFFFFFFFFu, dot, off);
            ksq += __shfl_xor_sync(0xFFFFFFFFu, ksq, off);
        }
        if (lane == 0)
            sim[p] = dot * rsqrtf(ksq + 1e-12f);
    }
    __syncthreads();

    // -- top-4, descending, lowest index on tie (matches jax.lax.top_k) --
    if (t == 0) {
        unsigned taken = 0u;
        for (int k = 0; k < TOPK; k++) {
            int   bi = 0;
            float bv = -3.4e38f;
            for (int p = 0; p < POOL; p++) {
                if ((taken >> p) & 1u) continue;
                if (sim[p] > bv) { bv = sim[p]; bi = p; }
            }
            sel[k] = bi;
            taken |= 1u << bi;
        }
        g_cnt[b] = 0;                        // reset for next graph replay
    }
    __syncthreads();

    // -- write selected e-prompt rows [8, 40): 32 rows x 192 float4 --
    float4* edst = out + ((size_t)b * T_OUT + L) * D4;
#pragma unroll
    for (int k = 0; k < TOPK; k++) {
        const float4* esrc = e_prompts + (size_t)sel[k] * L * D4;
#pragma unroll
        for (int i = 0; i < L; i++)
            edst[(k * L + i) * D4 + t] = esrc[i * D4 + t];
    }
}

// -------------------------------------------------------------------------
// Launch: single kernel, no dependent tail.
// -------------------------------------------------------------------------
extern "C" void kernel_launch(void* const* d_in, const int* in_sizes, int n_in,
                              void* d_out, int out_size)
{
    const float* x         = (const float*)d_in[0];   // [B,S,D]
    const float* g_prompts = (const float*)d_in[1];   // [NT,L,D]
    const float* e_prompts = (const float*)d_in[2];   // [POOL,L,D]
    const float* e_keys    = (const float*)d_in[3];   // [POOL,D]
    const float* cls_token = (const float*)d_in[4];   // [1,1,D]
    const int*   task_id   = (const int*)d_in[5];     // scalar
    float*       out       = (float*)d_out;           // [B,T_OUT,D]

    dim3 grid(CHUNKS + 1, B);
    fused_kernel<<<grid, D4>>>(
        reinterpret_cast<const float4*>(x),
        reinterpret_cast<float4*>(out),
        reinterpret_cast<const float4*>(g_prompts),
        reinterpret_cast<const float4*>(cls_token),
        e_keys,
        reinterpret_cast<const float4*>(e_prompts),
        task_id);
}